// round 9
// baseline (speedup 1.0000x reference)
#include <cuda_runtime.h>
#include <cuda_fp16.h>
#include <math.h>
#include <stdint.h>

// Problem constants
#define BB   2
#define NN   4096
#define HID  512
#define NH   8
#define HD   64
#define MTOK (BB*NN)          // 8192 tokens
#define QSCALE 0.04419417382415922f   // 1/sqrt(512)

// Scratch (device globals; no allocations allowed)
static __device__ __half g_xh[(size_t)MTOK*HID], g_xl[(size_t)MTOK*HID];   // x split
static __device__ __half g_wth[(size_t)3*HID*HID], g_wtl[(size_t)3*HID*HID]; // Wq/Wk/Wv transposed [n][k] split
static __device__ __half g_woth[(size_t)HID*HID], g_wotl[(size_t)HID*HID];   // Wo transposed split
static __device__ __half g_q[(size_t)BB*NH*NN*HD];    // [b,h,n,d] fp16
static __device__ __half g_k[(size_t)BB*NH*NN*HD];
static __device__ __half g_v[(size_t)BB*NH*NN*HD];
static __device__ __half g_ah[(size_t)MTOK*HID], g_al[(size_t)MTOK*HID];   // attention out split

// ---------------------------------------------------------------------------
// Helpers
// ---------------------------------------------------------------------------
__device__ __forceinline__ void mma_f16(float* d, const unsigned* a, const unsigned* b) {
    asm volatile(
        "mma.sync.aligned.m16n8k16.row.col.f32.f16.f16.f32 "
        "{%0,%1,%2,%3}, {%4,%5,%6,%7}, {%8,%9}, {%0,%1,%2,%3};"
        : "+f"(d[0]), "+f"(d[1]), "+f"(d[2]), "+f"(d[3])
        : "r"(a[0]), "r"(a[1]), "r"(a[2]), "r"(a[3]), "r"(b[0]), "r"(b[1]));
}
__device__ __forceinline__ void ldmx4(uint32_t* r, uint32_t saddr) {
    asm volatile("ldmatrix.sync.aligned.m8n8.x4.shared.b16 {%0,%1,%2,%3}, [%4];"
                 : "=r"(r[0]), "=r"(r[1]), "=r"(r[2]), "=r"(r[3]) : "r"(saddr));
}
__device__ __forceinline__ void ldmx2(uint32_t& r0, uint32_t& r1, uint32_t saddr) {
    asm volatile("ldmatrix.sync.aligned.m8n8.x2.shared.b16 {%0,%1}, [%2];"
                 : "=r"(r0), "=r"(r1) : "r"(saddr));
}
__device__ __forceinline__ void ldmx2t(uint32_t& r0, uint32_t& r1, uint32_t saddr) {
    asm volatile("ldmatrix.sync.aligned.m8n8.x2.trans.shared.b16 {%0,%1}, [%2];"
                 : "=r"(r0), "=r"(r1) : "r"(saddr));
}
__device__ __forceinline__ void cp_async16_u(unsigned saddr, const void* gmem) {
    asm volatile("cp.async.cg.shared.global [%0], [%1], 16;" :: "r"(saddr), "l"(gmem));
}
#define CP_COMMIT() asm volatile("cp.async.commit_group;")
#define CP_WAIT1()  asm volatile("cp.async.wait_group 1;")
#define CP_WAIT0()  asm volatile("cp.async.wait_group 0;")

__device__ __forceinline__ void f16_split(float v, __half& hi, __half& lo) {
    hi = __float2half_rn(v);
    lo = __float2half_rn(v - __half2float(hi));
}

// ---------------------------------------------------------------------------
// Prep kernel A: split x into fp16 hi/lo planes. 1M float4s.
// ---------------------------------------------------------------------------
__global__ __launch_bounds__(256) void split_x_kernel(const float* __restrict__ x)
{
    int i = blockIdx.x * 256 + threadIdx.x;       // 0 .. 1048575
    float4 v = ((const float4*)x)[i];
    __half hx, lx, hy, ly, hz, lz, hw, lw;
    f16_split(v.x, hx, lx);
    f16_split(v.y, hy, ly);
    f16_split(v.z, hz, lz);
    f16_split(v.w, hw, lw);
    ((__half2*)g_xh)[i*2]   = __halves2half2(hx, hy);
    ((__half2*)g_xh)[i*2+1] = __halves2half2(hz, hw);
    ((__half2*)g_xl)[i*2]   = __halves2half2(lx, ly);
    ((__half2*)g_xl)[i*2+1] = __halves2half2(lz, lw);
}

// ---------------------------------------------------------------------------
// Prep kernel B: transpose + split the 4 weight matrices.
// ---------------------------------------------------------------------------
__global__ __launch_bounds__(256) void split_w_kernel(
    const float* __restrict__ Wq, const float* __restrict__ Wk,
    const float* __restrict__ Wv, const float* __restrict__ Wo)
{
    __shared__ float t[32][33];
    const int z = blockIdx.z;
    const float* W = (z==0) ? Wq : (z==1) ? Wk : (z==2) ? Wv : Wo;
    __half* dh = (z < 3) ? (g_wth + (size_t)z * HID * HID) : g_woth;
    __half* dl = (z < 3) ? (g_wtl + (size_t)z * HID * HID) : g_wotl;
    const int n0 = blockIdx.x * 32, k0 = blockIdx.y * 32;
    const int tx = threadIdx.x, ty = threadIdx.y;

#pragma unroll
    for (int r = 0; r < 4; r++)
        t[ty + r*8][tx] = W[(size_t)(k0 + ty + r*8) * HID + n0 + tx];
    __syncthreads();
#pragma unroll
    for (int r = 0; r < 4; r++) {
        float v = t[tx][ty + r*8];     // = W[k0+tx][n0+ty+r*8]
        __half hv, lv;
        f16_split(v, hv, lv);
        size_t o = (size_t)(n0 + ty + r*8) * HID + k0 + tx;
        dh[o] = hv;
        dl[o] = lv;
    }
}

// ===========================================================================
// split-fp16 GEMM core (validated round 8)
// ===========================================================================
#define KP 40
#define PLANE (128*KP)
#define PB (PLANE*2)
#define GSMEM_BYTES (8*PB)

__device__ __forceinline__ void gemm_f16split(
    const __half* __restrict__ Agh, const __half* __restrict__ Agl,
    const __half* __restrict__ Bgh, const __half* __restrict__ Bgl,
    int tm0, int c0, __half* sm, float (*S)[8][4])
{
    const int tid  = threadIdx.x;
    const int warp = tid >> 5;
    const int lane = tid & 31;
    const int g  = lane >> 2;
    const int tg = lane & 3;
    const int wm0 = (warp >> 1) * 32;
    const int wn0 = (warp & 1) * 64;
    const uint32_t sb = (uint32_t)__cvta_generic_to_shared(sm);

#pragma unroll
    for (int mt = 0; mt < 2; mt++)
#pragma unroll
        for (int nt = 0; nt < 8; nt++)
#pragma unroll
            for (int j = 0; j < 4; j++) S[mt][nt][j] = 0.0f;

#define LOAD_STAGE(st, k0)                                                     \
    for (int i = tid; i < 512; i += 256) {                                     \
        int row = i >> 2, ch = i & 3;                                          \
        uint32_t so = (uint32_t)((st)*PB + row*(KP*2) + ch*16);                \
        size_t ga = (size_t)(tm0 + row) * HID + (k0) + ch*8;                   \
        size_t gb = (size_t)(c0  + row) * HID + (k0) + ch*8;                   \
        cp_async16_u(sb + so,        Agh + ga);                                \
        cp_async16_u(sb + 2*PB + so, Agl + ga);                                \
        cp_async16_u(sb + 4*PB + so, Bgh + gb);                                \
        cp_async16_u(sb + 6*PB + so, Bgl + gb);                                \
    }

    LOAD_STAGE(0, 0)
    CP_COMMIT();

    for (int kc = 0; kc < 16; kc++) {
        __syncthreads();
        if (kc + 1 < 16) {
            int ns = (kc + 1) & 1;
            int nk = (kc + 1) * 32;
            LOAD_STAGE(ns, nk)
            CP_COMMIT();
            CP_WAIT1();
        } else {
            CP_WAIT0();
        }
        __syncthreads();

        const int st = kc & 1;
        const __half* Ah = sm + st*PLANE;
        const __half* Al = sm + 2*PLANE + st*PLANE;
        const __half* Bh = sm + 4*PLANE + st*PLANE;
        const __half* Bl = sm + 6*PLANE + st*PLANE;

#pragma unroll
        for (int ks = 0; ks < 2; ks++) {
            const int ko = ks * 16;
            uint32_t ahi[2][4], alo[2][4];
#pragma unroll
            for (int mt = 0; mt < 2; mt++) {
                const __half* ah = Ah + (wm0 + mt*16)*KP + ko;
                const __half* al = Al + (wm0 + mt*16)*KP + ko;
                ahi[mt][0] = *(const uint32_t*)(ah + g*KP + 2*tg);
                ahi[mt][1] = *(const uint32_t*)(ah + (g+8)*KP + 2*tg);
                ahi[mt][2] = *(const uint32_t*)(ah + g*KP + 2*tg + 8);
                ahi[mt][3] = *(const uint32_t*)(ah + (g+8)*KP + 2*tg + 8);
                alo[mt][0] = *(const uint32_t*)(al + g*KP + 2*tg);
                alo[mt][1] = *(const uint32_t*)(al + (g+8)*KP + 2*tg);
                alo[mt][2] = *(const uint32_t*)(al + g*KP + 2*tg + 8);
                alo[mt][3] = *(const uint32_t*)(al + (g+8)*KP + 2*tg + 8);
            }
#pragma unroll
            for (int nt = 0; nt < 8; nt++) {
                const __half* bh = Bh + (wn0 + nt*8 + g)*KP + ko;
                const __half* bl = Bl + (wn0 + nt*8 + g)*KP + ko;
                uint32_t bhi[2], blo[2];
                bhi[0] = *(const uint32_t*)(bh + 2*tg);
                bhi[1] = *(const uint32_t*)(bh + 2*tg + 8);
                blo[0] = *(const uint32_t*)(bl + 2*tg);
                blo[1] = *(const uint32_t*)(bl + 2*tg + 8);
#pragma unroll
                for (int mt = 0; mt < 2; mt++) {
                    mma_f16(&S[mt][nt][0], ahi[mt], bhi);
                    mma_f16(&S[mt][nt][0], ahi[mt], blo);
                    mma_f16(&S[mt][nt][0], alo[mt], bhi);
                }
            }
        }
    }
#undef LOAD_STAGE
}

// ---------------------------------------------------------------------------
// Kernel 1: fused QKV projection (split-fp16). Outputs fp16 [b,h,n,d].
// ---------------------------------------------------------------------------
__global__ __launch_bounds__(256, 2) void qkv_f16_kernel(
    const float* __restrict__ bq, const float* __restrict__ bk,
    const float* __restrict__ bv)
{
    extern __shared__ __half gsm[];
    const int wsel = blockIdx.x >> 2;
    const int c0   = (blockIdx.x & 3) * 128;
    const __half* Bh = g_wth + (size_t)wsel * HID * HID;
    const __half* Bl = g_wtl + (size_t)wsel * HID * HID;
    const float* bias = (wsel==0) ? bq : ((wsel==1) ? bk : bv);
    __half* outb      = (wsel==0) ? g_q : ((wsel==1) ? g_k : g_v);
    const float scale = (wsel==0) ? QSCALE : 1.0f;
    const int tm0 = blockIdx.y * 128;

    float S[2][8][4];
    gemm_f16split(g_xh, g_xl, Bh, Bl, tm0, c0, gsm, S);

    const int tid  = threadIdx.x;
    const int warp = tid >> 5;
    const int lane = tid & 31;
    const int g  = lane >> 2;
    const int tg = lane & 3;
    const int wm0 = (warp >> 1) * 32;
    const int wn0 = (warp & 1) * 64;

    const int cbase = c0 + wn0;
    const int hh = cbase >> 6;

#pragma unroll
    for (int mt = 0; mt < 2; mt++) {
#pragma unroll
        for (int r = 0; r < 2; r++) {
            int t = tm0 + wm0 + mt*16 + r*8 + g;
            int b = t >> 12;
            int n = t & (NN - 1);
            __half* op = outb + (((size_t)(b * NH + hh)) * NN + n) * HD;
#pragma unroll
            for (int nt = 0; nt < 8; nt++) {
                int d0 = nt*8 + tg*2;
                float v0 = (S[mt][nt][2*r]   + bias[cbase + d0])     * scale;
                float v1 = (S[mt][nt][2*r+1] + bias[cbase + d0 + 1]) * scale;
                *(__half2*)(op + d0) = __floats2half2_rn(v0, v1);
            }
        }
    }
}

// ---------------------------------------------------------------------------
// Kernel 3: output projection (split-fp16). fp32 out.
// ---------------------------------------------------------------------------
__global__ __launch_bounds__(256, 2) void proj_f16_kernel(
    const float* __restrict__ bo, float* __restrict__ out)
{
    extern __shared__ __half gsm[];
    const int c0  = blockIdx.x * 128;
    const int tm0 = blockIdx.y * 128;

    float S[2][8][4];
    gemm_f16split(g_ah, g_al, g_woth, g_wotl, tm0, c0, gsm, S);

    const int tid  = threadIdx.x;
    const int warp = tid >> 5;
    const int lane = tid & 31;
    const int g  = lane >> 2;
    const int tg = lane & 3;
    const int wm0 = (warp >> 1) * 32;
    const int wn0 = (warp & 1) * 64;

#pragma unroll
    for (int mt = 0; mt < 2; mt++) {
#pragma unroll
        for (int r = 0; r < 2; r++) {
            int t = tm0 + wm0 + mt*16 + r*8 + g;
            float* op = out + (size_t)t * HID + c0 + wn0;
#pragma unroll
            for (int nt = 0; nt < 8; nt++) {
                int d0 = nt*8 + tg*2;
                float2 vv = make_float2(S[mt][nt][2*r]   + bo[c0 + wn0 + d0],
                                        S[mt][nt][2*r+1] + bo[c0 + wn0 + d0 + 1]);
                *(float2*)(op + d0) = vv;
            }
        }
    }
}

// ===========================================================================
// Kernel 2: flash attention, fp16 mma.sync, 8 warps x 16 query rows.
// 256 threads, __launch_bounds__(256,2) -> 16 warps/SM. ldmatrix fragments.
// ===========================================================================
#define QP 72
#define AOFF_Q  0
#define AOFF_K  (128*QP*2)                 // bytes
#define AOFF_V  (AOFF_K + 2*64*QP*2)
#define AOFF_P  (AOFF_V + 2*64*QP*2)
#define AOFF_MK (AOFF_P + 128*QP*2)
#define ATTN_SMEM (AOFF_MK + 2*64*4)
#define KVBUF (64*QP*2)

__global__ __launch_bounds__(256, 2) void attn_fp16_kernel(const float* __restrict__ mask)
{
    extern __shared__ char smc[];
    const uint32_t sbase = (uint32_t)__cvta_generic_to_shared(smc);
    __half* Ps = (__half*)(smc + AOFF_P);

    const int tid  = threadIdx.x;
    const int warp = tid >> 5;
    const int lane = tid & 31;
    const int g  = lane >> 2;
    const int tg = lane & 3;
    const int wq0 = warp * 16;             // 16 query rows per warp

    // ldmatrix lane->address components
    const int lrow8  = (lane & 7) + ((lane >> 3) & 1) * 8;   // x4 A row
    const int lcol16 = (lane >> 4) * 16;                     // x4 A col byte offset
    const int brow   = lane & 7;                             // x2 B row
    const int bcol16 = ((lane >> 3) & 1) * 16;               // x2 B col byte offset

    const int bh  = blockIdx.x;
    const int b   = bh >> 3;
    const int hd  = bh & 7;
    const int qt0 = blockIdx.y * 128;

    const __half* qb = g_q + (size_t)bh * NN * HD;
    const __half* kb = g_k + (size_t)bh * NN * HD;
    const __half* vb = g_v + (size_t)bh * NN * HD;
    const float*  mb = mask + (size_t)b * NN;

    // prologue: Q + tile 0 (K/V/mask) in one cp.async group
    for (int i = tid; i < 1024; i += 256) {
        int row = i >> 3, ch = i & 7;
        cp_async16_u(sbase + AOFF_Q + row*(QP*2) + ch*16,
                     qb + (size_t)(qt0 + row) * HD + ch*8);
    }
    for (int i = tid; i < 512; i += 256) {
        int row = i >> 3, ch = i & 7;
        cp_async16_u(sbase + AOFF_K + row*(QP*2) + ch*16, kb + (size_t)row * HD + ch*8);
        cp_async16_u(sbase + AOFF_V + row*(QP*2) + ch*16, vb + (size_t)row * HD + ch*8);
    }
    if (tid < 16) cp_async16_u(sbase + AOFF_MK + tid*16, mb + tid*4);
    CP_COMMIT();

    float mq[2];
    mq[0] = mb[qt0 + wq0 + g];
    mq[1] = mb[qt0 + wq0 + 8 + g];

    float O[8][4];
#pragma unroll
    for (int dt = 0; dt < 8; dt++)
#pragma unroll
        for (int j = 0; j < 4; j++) O[dt][j] = 0.0f;
    float lsum[2] = {0.f, 0.f};

    for (int it = 0; it < 64; it++) {
        const int buf = it & 1;
        __syncthreads();
        if (it + 1 < 64) {
            const int nb = (it + 1) & 1;
            const __half* kg = kb + (size_t)(it + 1) * 64 * HD;
            const __half* vg = vb + (size_t)(it + 1) * 64 * HD;
            for (int i = tid; i < 512; i += 256) {
                int row = i >> 3, ch = i & 7;
                cp_async16_u(sbase + AOFF_K + nb*KVBUF + row*(QP*2) + ch*16,
                             kg + (size_t)row * HD + ch*8);
                cp_async16_u(sbase + AOFF_V + nb*KVBUF + row*(QP*2) + ch*16,
                             vg + (size_t)row * HD + ch*8);
            }
            if (tid < 16) cp_async16_u(sbase + AOFF_MK + nb*256 + tid*16,
                                       mb + (it + 1)*64 + tid*4);
            CP_COMMIT();
            CP_WAIT1();
        } else {
            CP_WAIT0();
        }
        __syncthreads();

        const uint32_t kbase = sbase + AOFF_K + buf*KVBUF;
        const uint32_t vbase = sbase + AOFF_V + buf*KVBUF;
        const float*   mks  = (const float*)(smc + AOFF_MK + buf*256);

        // ---- S = Q @ K^T  (warp: 16 rows x 64 cols; 4 k-chunks of 16) ----
        float S[8][4];
#pragma unroll
        for (int nt = 0; nt < 8; nt++)
#pragma unroll
            for (int j = 0; j < 4; j++) S[nt][j] = 0.0f;

#pragma unroll
        for (int kc = 0; kc < 4; kc++) {
            uint32_t a[4];
            ldmx4(a, sbase + AOFF_Q + (uint32_t)((wq0 + lrow8)*(QP*2) + lcol16 + kc*32));
#pragma unroll
            for (int nt = 0; nt < 8; nt++) {
                uint32_t bf[2];
                ldmx2(bf[0], bf[1],
                      kbase + (uint32_t)((nt*8 + brow)*(QP*2) + bcol16 + kc*32));
                mma_f16(&S[nt][0], a, bf);
            }
        }

        // ---- softmax (no max subtraction; masked -> exp(-1e6) = 0) ----
#pragma unroll
        for (int nt = 0; nt < 8; nt++) {
            int c0 = nt*8 + 2*tg;
            float mk0 = mks[c0], mk1 = mks[c0 + 1];
            float p0 = __expf(S[nt][0] + (1.0f - mq[0]*mk0) * (-1.0e6f));
            float p1 = __expf(S[nt][1] + (1.0f - mq[0]*mk1) * (-1.0e6f));
            float p2 = __expf(S[nt][2] + (1.0f - mq[1]*mk0) * (-1.0e6f));
            float p3 = __expf(S[nt][3] + (1.0f - mq[1]*mk1) * (-1.0e6f));
            lsum[0] += p0 + p1;
            lsum[1] += p2 + p3;
            *(__half2*)(Ps + (wq0 + g)*QP + c0)     = __floats2half2_rn(p0, p1);
            *(__half2*)(Ps + (wq0 + g + 8)*QP + c0) = __floats2half2_rn(p2, p3);
        }
        __syncwarp();      // P rows warp-private

        // ---- O += P @ V  (4 k-chunks of 16 keys) ----
#pragma unroll
        for (int kc = 0; kc < 4; kc++) {
            uint32_t a[4];
            ldmx4(a, sbase + AOFF_P + (uint32_t)((wq0 + lrow8)*(QP*2) + lcol16 + kc*32));
#pragma unroll
            for (int dt = 0; dt < 8; dt++) {
                uint32_t bf[2];
                ldmx2t(bf[0], bf[1],
                       vbase + (uint32_t)((kc*16 + (lane & 15))*(QP*2) + dt*16));
                mma_f16(&O[dt][0], a, bf);
            }
        }
    }

    // ---- epilogue: normalize, split to fp16 hi/lo planes ----
#pragma unroll
    for (int r = 0; r < 2; r++) {
        float s = lsum[r];
        s += __shfl_xor_sync(0xffffffffu, s, 1);
        s += __shfl_xor_sync(0xffffffffu, s, 2);
        float inv = 1.0f / s;
        int row = qt0 + wq0 + r*8 + g;
        size_t base = ((size_t)(b * NN + row)) * HID + hd * HD;
#pragma unroll
        for (int dt = 0; dt < 8; dt++) {
            float v0 = O[dt][2*r] * inv;
            float v1 = O[dt][2*r+1] * inv;
            __half h0, l0, h1, l1;
            f16_split(v0, h0, l0);
            f16_split(v1, h1, l1);
            size_t o = base + dt*8 + 2*tg;
            *(__half2*)(g_ah + o) = __halves2half2(h0, h1);
            *(__half2*)(g_al + o) = __halves2half2(l0, l1);
        }
    }
}

// ---------------------------------------------------------------------------
extern "C" void kernel_launch(void* const* d_in, const int* in_sizes, int n_in,
                              void* d_out, int out_size)
{
    const float* x    = (const float*)d_in[0];
    const float* mask = (const float*)d_in[1];
    const float* Wq   = (const float*)d_in[2];
    const float* bq   = (const float*)d_in[3];
    const float* Wk   = (const float*)d_in[4];
    const float* bk   = (const float*)d_in[5];
    const float* Wv   = (const float*)d_in[6];
    const float* bv   = (const float*)d_in[7];
    const float* Wo   = (const float*)d_in[8];
    const float* bo   = (const float*)d_in[9];
    float* out = (float*)d_out;

    cudaFuncSetAttribute(attn_fp16_kernel,
                         cudaFuncAttributeMaxDynamicSharedMemorySize, ATTN_SMEM);
    cudaFuncSetAttribute(qkv_f16_kernel,
                         cudaFuncAttributeMaxDynamicSharedMemorySize, GSMEM_BYTES);
    cudaFuncSetAttribute(proj_f16_kernel,
                         cudaFuncAttributeMaxDynamicSharedMemorySize, GSMEM_BYTES);

    split_x_kernel<<<4096, 256>>>(x);
    split_w_kernel<<<dim3(16, 16, 4), dim3(32, 8)>>>(Wq, Wk, Wv, Wo);

    dim3 qkv_grid(12, MTOK / 128);
    qkv_f16_kernel<<<qkv_grid, 256, GSMEM_BYTES>>>(bq, bk, bv);

    dim3 attn_grid(BB * NH, NN / 128);
    attn_fp16_kernel<<<attn_grid, 256, ATTN_SMEM>>>(mask);

    dim3 proj_grid(HID / 128, MTOK / 128);
    proj_f16_kernel<<<proj_grid, 256, GSMEM_BYTES>>>(bo, out);
}

// round 11
// speedup vs baseline: 1.1087x; 1.1087x over previous
#include <cuda_runtime.h>
#include <cuda_fp16.h>
#include <math.h>
#include <stdint.h>

// Problem constants
#define BB   2
#define NN   4096
#define HID  512
#define NH   8
#define HD   64
#define MTOK (BB*NN)          // 8192 tokens
#define QSCALE 0.04419417382415922f   // 1/sqrt(512)

// Scratch (device globals; no allocations allowed)
static __device__ __half g_xh[(size_t)MTOK*HID], g_xl[(size_t)MTOK*HID];   // x split
static __device__ __half g_wth[(size_t)3*HID*HID], g_wtl[(size_t)3*HID*HID]; // Wq/Wk/Wv transposed [n][k] split
static __device__ __half g_woth[(size_t)HID*HID], g_wotl[(size_t)HID*HID];   // Wo transposed split
static __device__ __half g_q[(size_t)BB*NH*NN*HD];    // [b,h,n,d] fp16
static __device__ __half g_k[(size_t)BB*NH*NN*HD];
static __device__ __half g_v[(size_t)BB*NH*NN*HD];
static __device__ __half g_ah[(size_t)MTOK*HID], g_al[(size_t)MTOK*HID];   // attention out split

// ---------------------------------------------------------------------------
// Helpers
// ---------------------------------------------------------------------------
__device__ __forceinline__ void mma_f16(float* d, const unsigned* a, const unsigned* b) {
    asm volatile(
        "mma.sync.aligned.m16n8k16.row.col.f32.f16.f16.f32 "
        "{%0,%1,%2,%3}, {%4,%5,%6,%7}, {%8,%9}, {%0,%1,%2,%3};"
        : "+f"(d[0]), "+f"(d[1]), "+f"(d[2]), "+f"(d[3])
        : "r"(a[0]), "r"(a[1]), "r"(a[2]), "r"(a[3]), "r"(b[0]), "r"(b[1]));
}
__device__ __forceinline__ void ldmx4(uint32_t* r, uint32_t saddr) {
    asm volatile("ldmatrix.sync.aligned.m8n8.x4.shared.b16 {%0,%1,%2,%3}, [%4];"
                 : "=r"(r[0]), "=r"(r[1]), "=r"(r[2]), "=r"(r[3]) : "r"(saddr));
}
__device__ __forceinline__ void ldmx4t(uint32_t* r, uint32_t saddr) {
    asm volatile("ldmatrix.sync.aligned.m8n8.x4.trans.shared.b16 {%0,%1,%2,%3}, [%4];"
                 : "=r"(r[0]), "=r"(r[1]), "=r"(r[2]), "=r"(r[3]) : "r"(saddr));
}
__device__ __forceinline__ void cp_async16_u(unsigned saddr, const void* gmem) {
    asm volatile("cp.async.cg.shared.global [%0], [%1], 16;" :: "r"(saddr), "l"(gmem));
}
#define CP_COMMIT() asm volatile("cp.async.commit_group;")
#define CP_WAIT1()  asm volatile("cp.async.wait_group 1;")
#define CP_WAIT0()  asm volatile("cp.async.wait_group 0;")

__device__ __forceinline__ void f16_split(float v, __half& hi, __half& lo) {
    hi = __float2half_rn(v);
    lo = __float2half_rn(v - __half2float(hi));
}

// ---------------------------------------------------------------------------
// Prep kernel A: split x into fp16 hi/lo planes. 1M float4s.
// ---------------------------------------------------------------------------
__global__ __launch_bounds__(256) void split_x_kernel(const float* __restrict__ x)
{
    int i = blockIdx.x * 256 + threadIdx.x;       // 0 .. 1048575
    float4 v = ((const float4*)x)[i];
    __half hx, lx, hy, ly, hz, lz, hw, lw;
    f16_split(v.x, hx, lx);
    f16_split(v.y, hy, ly);
    f16_split(v.z, hz, lz);
    f16_split(v.w, hw, lw);
    ((__half2*)g_xh)[i*2]   = __halves2half2(hx, hy);
    ((__half2*)g_xh)[i*2+1] = __halves2half2(hz, hw);
    ((__half2*)g_xl)[i*2]   = __halves2half2(lx, ly);
    ((__half2*)g_xl)[i*2+1] = __halves2half2(lz, lw);
}

// ---------------------------------------------------------------------------
// Prep kernel B: transpose + split the 4 weight matrices.
// ---------------------------------------------------------------------------
__global__ __launch_bounds__(256) void split_w_kernel(
    const float* __restrict__ Wq, const float* __restrict__ Wk,
    const float* __restrict__ Wv, const float* __restrict__ Wo)
{
    __shared__ float t[32][33];
    const int z = blockIdx.z;
    const float* W = (z==0) ? Wq : (z==1) ? Wk : (z==2) ? Wv : Wo;
    __half* dh = (z < 3) ? (g_wth + (size_t)z * HID * HID) : g_woth;
    __half* dl = (z < 3) ? (g_wtl + (size_t)z * HID * HID) : g_wotl;
    const int n0 = blockIdx.x * 32, k0 = blockIdx.y * 32;
    const int tx = threadIdx.x, ty = threadIdx.y;

#pragma unroll
    for (int r = 0; r < 4; r++)
        t[ty + r*8][tx] = W[(size_t)(k0 + ty + r*8) * HID + n0 + tx];
    __syncthreads();
#pragma unroll
    for (int r = 0; r < 4; r++) {
        float v = t[tx][ty + r*8];     // = W[k0+tx][n0+ty+r*8]
        __half hv, lv;
        f16_split(v, hv, lv);
        size_t o = (size_t)(n0 + ty + r*8) * HID + k0 + tx;
        dh[o] = hv;
        dl[o] = lv;
    }
}

// ===========================================================================
// split-fp16 GEMM core (validated round 8)
// ===========================================================================
#define KP 40
#define PLANE (128*KP)
#define PB (PLANE*2)
#define GSMEM_BYTES (8*PB)

__device__ __forceinline__ void gemm_f16split(
    const __half* __restrict__ Agh, const __half* __restrict__ Agl,
    const __half* __restrict__ Bgh, const __half* __restrict__ Bgl,
    int tm0, int c0, __half* sm, float (*S)[8][4])
{
    const int tid  = threadIdx.x;
    const int warp = tid >> 5;
    const int lane = tid & 31;
    const int g  = lane >> 2;
    const int tg = lane & 3;
    const int wm0 = (warp >> 1) * 32;
    const int wn0 = (warp & 1) * 64;
    const uint32_t sb = (uint32_t)__cvta_generic_to_shared(sm);

#pragma unroll
    for (int mt = 0; mt < 2; mt++)
#pragma unroll
        for (int nt = 0; nt < 8; nt++)
#pragma unroll
            for (int j = 0; j < 4; j++) S[mt][nt][j] = 0.0f;

#define LOAD_STAGE(st, k0)                                                     \
    for (int i = tid; i < 512; i += 256) {                                     \
        int row = i >> 2, ch = i & 3;                                          \
        uint32_t so = (uint32_t)((st)*PB + row*(KP*2) + ch*16);                \
        size_t ga = (size_t)(tm0 + row) * HID + (k0) + ch*8;                   \
        size_t gb = (size_t)(c0  + row) * HID + (k0) + ch*8;                   \
        cp_async16_u(sb + so,        Agh + ga);                                \
        cp_async16_u(sb + 2*PB + so, Agl + ga);                                \
        cp_async16_u(sb + 4*PB + so, Bgh + gb);                                \
        cp_async16_u(sb + 6*PB + so, Bgl + gb);                                \
    }

    LOAD_STAGE(0, 0)
    CP_COMMIT();

    for (int kc = 0; kc < 16; kc++) {
        __syncthreads();
        if (kc + 1 < 16) {
            int ns = (kc + 1) & 1;
            int nk = (kc + 1) * 32;
            LOAD_STAGE(ns, nk)
            CP_COMMIT();
            CP_WAIT1();
        } else {
            CP_WAIT0();
        }
        __syncthreads();

        const int st = kc & 1;
        const __half* Ah = sm + st*PLANE;
        const __half* Al = sm + 2*PLANE + st*PLANE;
        const __half* Bh = sm + 4*PLANE + st*PLANE;
        const __half* Bl = sm + 6*PLANE + st*PLANE;

#pragma unroll
        for (int ks = 0; ks < 2; ks++) {
            const int ko = ks * 16;
            uint32_t ahi[2][4], alo[2][4];
#pragma unroll
            for (int mt = 0; mt < 2; mt++) {
                const __half* ah = Ah + (wm0 + mt*16)*KP + ko;
                const __half* al = Al + (wm0 + mt*16)*KP + ko;
                ahi[mt][0] = *(const uint32_t*)(ah + g*KP + 2*tg);
                ahi[mt][1] = *(const uint32_t*)(ah + (g+8)*KP + 2*tg);
                ahi[mt][2] = *(const uint32_t*)(ah + g*KP + 2*tg + 8);
                ahi[mt][3] = *(const uint32_t*)(ah + (g+8)*KP + 2*tg + 8);
                alo[mt][0] = *(const uint32_t*)(al + g*KP + 2*tg);
                alo[mt][1] = *(const uint32_t*)(al + (g+8)*KP + 2*tg);
                alo[mt][2] = *(const uint32_t*)(al + g*KP + 2*tg + 8);
                alo[mt][3] = *(const uint32_t*)(al + (g+8)*KP + 2*tg + 8);
            }
#pragma unroll
            for (int nt = 0; nt < 8; nt++) {
                const __half* bh = Bh + (wn0 + nt*8 + g)*KP + ko;
                const __half* bl = Bl + (wn0 + nt*8 + g)*KP + ko;
                uint32_t bhi[2], blo[2];
                bhi[0] = *(const uint32_t*)(bh + 2*tg);
                bhi[1] = *(const uint32_t*)(bh + 2*tg + 8);
                blo[0] = *(const uint32_t*)(bl + 2*tg);
                blo[1] = *(const uint32_t*)(bl + 2*tg + 8);
#pragma unroll
                for (int mt = 0; mt < 2; mt++) {
                    mma_f16(&S[mt][nt][0], ahi[mt], bhi);
                    mma_f16(&S[mt][nt][0], ahi[mt], blo);
                    mma_f16(&S[mt][nt][0], alo[mt], bhi);
                }
            }
        }
    }
#undef LOAD_STAGE
}

// ---------------------------------------------------------------------------
// Kernel 1: fused QKV projection (split-fp16). Outputs fp16 [b,h,n,d].
// ---------------------------------------------------------------------------
__global__ __launch_bounds__(256, 2) void qkv_f16_kernel(
    const float* __restrict__ bq, const float* __restrict__ bk,
    const float* __restrict__ bv)
{
    extern __shared__ __half gsm[];
    const int wsel = blockIdx.x >> 2;
    const int c0   = (blockIdx.x & 3) * 128;
    const __half* Bh = g_wth + (size_t)wsel * HID * HID;
    const __half* Bl = g_wtl + (size_t)wsel * HID * HID;
    const float* bias = (wsel==0) ? bq : ((wsel==1) ? bk : bv);
    __half* outb      = (wsel==0) ? g_q : ((wsel==1) ? g_k : g_v);
    const float scale = (wsel==0) ? QSCALE : 1.0f;
    const int tm0 = blockIdx.y * 128;

    float S[2][8][4];
    gemm_f16split(g_xh, g_xl, Bh, Bl, tm0, c0, gsm, S);

    const int tid  = threadIdx.x;
    const int warp = tid >> 5;
    const int lane = tid & 31;
    const int g  = lane >> 2;
    const int tg = lane & 3;
    const int wm0 = (warp >> 1) * 32;
    const int wn0 = (warp & 1) * 64;

    const int cbase = c0 + wn0;
    const int hh = cbase >> 6;

#pragma unroll
    for (int mt = 0; mt < 2; mt++) {
#pragma unroll
        for (int r = 0; r < 2; r++) {
            int t = tm0 + wm0 + mt*16 + r*8 + g;
            int b = t >> 12;
            int n = t & (NN - 1);
            __half* op = outb + (((size_t)(b * NH + hh)) * NN + n) * HD;
#pragma unroll
            for (int nt = 0; nt < 8; nt++) {
                int d0 = nt*8 + tg*2;
                float v0 = (S[mt][nt][2*r]   + bias[cbase + d0])     * scale;
                float v1 = (S[mt][nt][2*r+1] + bias[cbase + d0 + 1]) * scale;
                *(__half2*)(op + d0) = __floats2half2_rn(v0, v1);
            }
        }
    }
}

// ---------------------------------------------------------------------------
// Kernel 3: output projection (split-fp16). fp32 out.
// ---------------------------------------------------------------------------
__global__ __launch_bounds__(256, 2) void proj_f16_kernel(
    const float* __restrict__ bo, float* __restrict__ out)
{
    extern __shared__ __half gsm[];
    const int c0  = blockIdx.x * 128;
    const int tm0 = blockIdx.y * 128;

    float S[2][8][4];
    gemm_f16split(g_ah, g_al, g_woth, g_wotl, tm0, c0, gsm, S);

    const int tid  = threadIdx.x;
    const int warp = tid >> 5;
    const int lane = tid & 31;
    const int g  = lane >> 2;
    const int tg = lane & 3;
    const int wm0 = (warp >> 1) * 32;
    const int wn0 = (warp & 1) * 64;

#pragma unroll
    for (int mt = 0; mt < 2; mt++) {
#pragma unroll
        for (int r = 0; r < 2; r++) {
            int t = tm0 + wm0 + mt*16 + r*8 + g;
            float* op = out + (size_t)t * HID + c0 + wn0;
#pragma unroll
            for (int nt = 0; nt < 8; nt++) {
                int d0 = nt*8 + tg*2;
                float2 vv = make_float2(S[mt][nt][2*r]   + bo[c0 + wn0 + d0],
                                        S[mt][nt][2*r+1] + bo[c0 + wn0 + d0 + 1]);
                *(float2*)(op + d0) = vv;
            }
        }
    }
}

// ===========================================================================
// Kernel 2: flash attention, fp16 mma.sync, 8 warps x 16 query rows.
// All-ones mask fast path (bit-identical: bias is exactly 0 when mask==1).
// B operands fetched via ldmatrix.x4 (2 n-tiles / 2 d-tiles per instr).
// ===========================================================================
#define QP 72
#define AOFF_Q  0
#define AOFF_K  (128*QP*2)                 // bytes
#define AOFF_V  (AOFF_K + 2*64*QP*2)
#define AOFF_P  (AOFF_V + 2*64*QP*2)
#define AOFF_MK (AOFF_P + 128*QP*2)
#define ATTN_SMEM (AOFF_MK + 2*64*4)
#define KVBUF (64*QP*2)

__global__ __launch_bounds__(256, 2) void attn_fp16_kernel(const float* __restrict__ mask)
{
    extern __shared__ char smc[];
    const uint32_t sbase = (uint32_t)__cvta_generic_to_shared(smc);
    __half* Ps = (__half*)(smc + AOFF_P);

    const int tid  = threadIdx.x;
    const int warp = tid >> 5;
    const int lane = tid & 31;
    const int g  = lane >> 2;
    const int tg = lane & 3;
    const int wq0 = warp * 16;             // 16 query rows per warp

    // ldmatrix lane->address components
    const int lrow8  = (lane & 7) + ((lane >> 3) & 1) * 8;   // x4 A row
    const int lcol16 = (lane >> 4) * 16;                     // x4 A col byte offset
    // K B x4: lanes 0-7: rows +0 @k0 | 8-15: rows +0 @k8 | 16-23: rows +8 @k0 | 24-31: rows +8 @k8
    const int kbrow  = (lane & 7) + ((lane >> 4) & 1) * 8;
    const int kbcol  = ((lane >> 3) & 1) * 16;
    // V B x4 trans: lanes 0-7 keys+0 @d0 | 8-15 keys+8 @d0 | 16-23 keys+0 @d+16B | 24-31 keys+8 @d+16B
    const int vbrow  = lane & 15;
    const int vbcol  = (lane >> 4) * 16;

    const int bh  = blockIdx.x;
    const int b   = bh >> 3;
    const int hd  = bh & 7;
    const int qt0 = blockIdx.y * 128;

    const __half* qb = g_q + (size_t)bh * NN * HD;
    const __half* kb = g_k + (size_t)bh * NN * HD;
    const __half* vb = g_v + (size_t)bh * NN * HD;
    const float*  mb = mask + (size_t)b * NN;

    // ---- all-ones mask detection (uniform per block) ----
    int ok = 1;
    for (int i = tid; i < NN / 4; i += 256) {
        float4 mv = ((const float4*)mb)[i];
        ok &= (mv.x == 1.0f) & (mv.y == 1.0f) & (mv.z == 1.0f) & (mv.w == 1.0f);
    }
    const int allone = __syncthreads_and(ok);

    // prologue: Q + tile 0 (K/V/mask) in one cp.async group
    for (int i = tid; i < 1024; i += 256) {
        int row = i >> 3, ch = i & 7;
        cp_async16_u(sbase + AOFF_Q + row*(QP*2) + ch*16,
                     qb + (size_t)(qt0 + row) * HD + ch*8);
    }
    for (int i = tid; i < 512; i += 256) {
        int row = i >> 3, ch = i & 7;
        cp_async16_u(sbase + AOFF_K + row*(QP*2) + ch*16, kb + (size_t)row * HD + ch*8);
        cp_async16_u(sbase + AOFF_V + row*(QP*2) + ch*16, vb + (size_t)row * HD + ch*8);
    }
    if (!allone && tid < 16) cp_async16_u(sbase + AOFF_MK + tid*16, mb + tid*4);
    CP_COMMIT();

    float mq[2];
    mq[0] = mb[qt0 + wq0 + g];
    mq[1] = mb[qt0 + wq0 + 8 + g];

    float O[8][4];
#pragma unroll
    for (int dt = 0; dt < 8; dt++)
#pragma unroll
        for (int j = 0; j < 4; j++) O[dt][j] = 0.0f;
    float lsum[2] = {0.f, 0.f};

    for (int it = 0; it < 64; it++) {
        const int buf = it & 1;
        __syncthreads();
        if (it + 1 < 64) {
            const int nb = (it + 1) & 1;
            const __half* kg = kb + (size_t)(it + 1) * 64 * HD;
            const __half* vg = vb + (size_t)(it + 1) * 64 * HD;
            for (int i = tid; i < 512; i += 256) {
                int row = i >> 3, ch = i & 7;
                cp_async16_u(sbase + AOFF_K + nb*KVBUF + row*(QP*2) + ch*16,
                             kg + (size_t)row * HD + ch*8);
                cp_async16_u(sbase + AOFF_V + nb*KVBUF + row*(QP*2) + ch*16,
                             vg + (size_t)row * HD + ch*8);
            }
            if (!allone && tid < 16) cp_async16_u(sbase + AOFF_MK + nb*256 + tid*16,
                                                  mb + (it + 1)*64 + tid*4);
            CP_COMMIT();
            CP_WAIT1();
        } else {
            CP_WAIT0();
        }
        __syncthreads();

        const uint32_t kbase = sbase + AOFF_K + buf*KVBUF;
        const uint32_t vbase = sbase + AOFF_V + buf*KVBUF;
        const float*   mks  = (const float*)(smc + AOFF_MK + buf*256);

        // ---- S = Q @ K^T  (warp: 16 rows x 64 cols; 4 k-chunks of 16) ----
        float S[8][4];
#pragma unroll
        for (int nt = 0; nt < 8; nt++)
#pragma unroll
            for (int j = 0; j < 4; j++) S[nt][j] = 0.0f;

#pragma unroll
        for (int kc = 0; kc < 4; kc++) {
            uint32_t a[4];
            ldmx4(a, sbase + AOFF_Q + (uint32_t)((wq0 + lrow8)*(QP*2) + lcol16 + kc*32));
#pragma unroll
            for (int ntp = 0; ntp < 4; ntp++) {
                uint32_t bf[4];
                ldmx4(bf, kbase + (uint32_t)((ntp*16 + kbrow)*(QP*2) + kbcol + kc*32));
                mma_f16(&S[2*ntp][0],   a, bf);
                mma_f16(&S[2*ntp+1][0], a, bf + 2);
            }
        }

        // ---- softmax ----
        if (allone) {
            // mask==1 everywhere: bias is exactly 0 -> p = exp(S)
#pragma unroll
            for (int nt = 0; nt < 8; nt++) {
                int c0 = nt*8 + 2*tg;
                float p0 = __expf(S[nt][0]);
                float p1 = __expf(S[nt][1]);
                float p2 = __expf(S[nt][2]);
                float p3 = __expf(S[nt][3]);
                lsum[0] += p0 + p1;
                lsum[1] += p2 + p3;
                *(__half2*)(Ps + (wq0 + g)*QP + c0)     = __floats2half2_rn(p0, p1);
                *(__half2*)(Ps + (wq0 + g + 8)*QP + c0) = __floats2half2_rn(p2, p3);
            }
        } else {
#pragma unroll
            for (int nt = 0; nt < 8; nt++) {
                int c0 = nt*8 + 2*tg;
                float mk0 = mks[c0], mk1 = mks[c0 + 1];
                float p0 = __expf(S[nt][0] + (1.0f - mq[0]*mk0) * (-1.0e6f));
                float p1 = __expf(S[nt][1] + (1.0f - mq[0]*mk1) * (-1.0e6f));
                float p2 = __expf(S[nt][2] + (1.0f - mq[1]*mk0) * (-1.0e6f));
                float p3 = __expf(S[nt][3] + (1.0f - mq[1]*mk1) * (-1.0e6f));
                lsum[0] += p0 + p1;
                lsum[1] += p2 + p3;
                *(__half2*)(Ps + (wq0 + g)*QP + c0)     = __floats2half2_rn(p0, p1);
                *(__half2*)(Ps + (wq0 + g + 8)*QP + c0) = __floats2half2_rn(p2, p3);
            }
        }
        __syncwarp();      // P rows warp-private

        // ---- O += P @ V  (4 k-chunks of 16 keys; 2 d-tiles per ldmx4t) ----
#pragma unroll
        for (int kc = 0; kc < 4; kc++) {
            uint32_t a[4];
            ldmx4(a, sbase + AOFF_P + (uint32_t)((wq0 + lrow8)*(QP*2) + lcol16 + kc*32));
#pragma unroll
            for (int dtp = 0; dtp < 4; dtp++) {
                uint32_t bf[4];
                ldmx4t(bf, vbase + (uint32_t)((kc*16 + vbrow)*(QP*2) + dtp*32 + vbcol));
                mma_f16(&O[2*dtp][0],   a, bf);
                mma_f16(&O[2*dtp+1][0], a, bf + 2);
            }
        }
    }

    // ---- epilogue: normalize, split to fp16 hi/lo planes ----
#pragma unroll
    for (int r = 0; r < 2; r++) {
        float s = lsum[r];
        s += __shfl_xor_sync(0xffffffffu, s, 1);
        s += __shfl_xor_sync(0xffffffffu, s, 2);
        float inv = 1.0f / s;
        int row = qt0 + wq0 + r*8 + g;
        size_t base = ((size_t)(b * NN + row)) * HID + hd * HD;
#pragma unroll
        for (int dt = 0; dt < 8; dt++) {
            float v0 = O[dt][2*r] * inv;
            float v1 = O[dt][2*r+1] * inv;
            __half h0, l0, h1, l1;
            f16_split(v0, h0, l0);
            f16_split(v1, h1, l1);
            size_t o = base + dt*8 + 2*tg;
            *(__half2*)(g_ah + o) = __halves2half2(h0, h1);
            *(__half2*)(g_al + o) = __halves2half2(l0, l1);
        }
    }
}

// ---------------------------------------------------------------------------
extern "C" void kernel_launch(void* const* d_in, const int* in_sizes, int n_in,
                              void* d_out, int out_size)
{
    const float* x    = (const float*)d_in[0];
    const float* mask = (const float*)d_in[1];
    const float* Wq   = (const float*)d_in[2];
    const float* bq   = (const float*)d_in[3];
    const float* Wk   = (const float*)d_in[4];
    const float* bk   = (const float*)d_in[5];
    const float* Wv   = (const float*)d_in[6];
    const float* bv   = (const float*)d_in[7];
    const float* Wo   = (const float*)d_in[8];
    const float* bo   = (const float*)d_in[9];
    float* out = (float*)d_out;

    cudaFuncSetAttribute(attn_fp16_kernel,
                         cudaFuncAttributeMaxDynamicSharedMemorySize, ATTN_SMEM);
    cudaFuncSetAttribute(qkv_f16_kernel,
                         cudaFuncAttributeMaxDynamicSharedMemorySize, GSMEM_BYTES);
    cudaFuncSetAttribute(proj_f16_kernel,
                         cudaFuncAttributeMaxDynamicSharedMemorySize, GSMEM_BYTES);

    split_x_kernel<<<4096, 256>>>(x);
    split_w_kernel<<<dim3(16, 16, 4), dim3(32, 8)>>>(Wq, Wk, Wv, Wo);

    dim3 qkv_grid(12, MTOK / 128);
    qkv_f16_kernel<<<qkv_grid, 256, GSMEM_BYTES>>>(bq, bk, bv);

    dim3 attn_grid(BB * NH, NN / 128);
    attn_fp16_kernel<<<attn_grid, 256, ATTN_SMEM>>>(mask);

    dim3 proj_grid(HID / 128, MTOK / 128);
    proj_f16_kernel<<<proj_grid, 256, GSMEM_BYTES>>>(bo, out);
}

// round 15
// speedup vs baseline: 1.1592x; 1.0455x over previous
#include <cuda_runtime.h>
#include <cuda_fp16.h>
#include <math.h>
#include <stdint.h>

// Problem constants
#define BB   2
#define NN   4096
#define HID  512
#define NH   8
#define HD   64
#define MTOK (BB*NN)          // 8192 tokens
#define QSCALE 0.04419417382415922f   // 1/sqrt(512)

// Scratch (device globals; no allocations allowed)
static __device__ __half g_xh[(size_t)MTOK*HID], g_xl[(size_t)MTOK*HID];   // x split
static __device__ __half g_wth[(size_t)3*HID*HID], g_wtl[(size_t)3*HID*HID]; // Wq/Wk/Wv transposed [n][k] split
static __device__ __half g_woth[(size_t)HID*HID], g_wotl[(size_t)HID*HID];   // Wo transposed split
static __device__ __half g_q[(size_t)BB*NH*NN*HD];    // [b,h,n,d] fp16
static __device__ __half g_k[(size_t)BB*NH*NN*HD];
static __device__ __half g_v[(size_t)BB*NH*NN*HD];
static __device__ __half g_ah[(size_t)MTOK*HID], g_al[(size_t)MTOK*HID];   // attention out split

// ---------------------------------------------------------------------------
// Helpers
// ---------------------------------------------------------------------------
__device__ __forceinline__ void mma_f16(float* d, const unsigned* a, const unsigned* b) {
    asm volatile(
        "mma.sync.aligned.m16n8k16.row.col.f32.f16.f16.f32 "
        "{%0,%1,%2,%3}, {%4,%5,%6,%7}, {%8,%9}, {%0,%1,%2,%3};"
        : "+f"(d[0]), "+f"(d[1]), "+f"(d[2]), "+f"(d[3])
        : "r"(a[0]), "r"(a[1]), "r"(a[2]), "r"(a[3]), "r"(b[0]), "r"(b[1]));
}
__device__ __forceinline__ void ldmx4(uint32_t* r, uint32_t saddr) {
    asm volatile("ldmatrix.sync.aligned.m8n8.x4.shared.b16 {%0,%1,%2,%3}, [%4];"
                 : "=r"(r[0]), "=r"(r[1]), "=r"(r[2]), "=r"(r[3]) : "r"(saddr));
}
__device__ __forceinline__ void ldmx4t(uint32_t* r, uint32_t saddr) {
    asm volatile("ldmatrix.sync.aligned.m8n8.x4.trans.shared.b16 {%0,%1,%2,%3}, [%4];"
                 : "=r"(r[0]), "=r"(r[1]), "=r"(r[2]), "=r"(r[3]) : "r"(saddr));
}
__device__ __forceinline__ void cp_async16_u(unsigned saddr, const void* gmem) {
    asm volatile("cp.async.cg.shared.global [%0], [%1], 16;" :: "r"(saddr), "l"(gmem));
}
#define CP_COMMIT() asm volatile("cp.async.commit_group;")
#define CP_WAIT1()  asm volatile("cp.async.wait_group 1;")
#define CP_WAIT0()  asm volatile("cp.async.wait_group 0;")

__device__ __forceinline__ void f16_split(float v, __half& hi, __half& lo) {
    hi = __float2half_rn(v);
    lo = __float2half_rn(v - __half2float(hi));
}
// pack two floats into one u32: lower half = f16(lo), upper half = f16(hi) —
// same bits as __floats2half2_rn(lo, hi), usable directly as an MMA operand.
__device__ __forceinline__ uint32_t h2u_pack(float lo, float hi) {
    uint32_t r;
    asm("cvt.rn.f16x2.f32 %0, %1, %2;" : "=r"(r) : "f"(hi), "f"(lo));
    return r;
}

// ---------------------------------------------------------------------------
// Prep kernel A: split x into fp16 hi/lo planes. 1M float4s.
// ---------------------------------------------------------------------------
__global__ __launch_bounds__(256) void split_x_kernel(const float* __restrict__ x)
{
    int i = blockIdx.x * 256 + threadIdx.x;       // 0 .. 1048575
    float4 v = ((const float4*)x)[i];
    __half hx, lx, hy, ly, hz, lz, hw, lw;
    f16_split(v.x, hx, lx);
    f16_split(v.y, hy, ly);
    f16_split(v.z, hz, lz);
    f16_split(v.w, hw, lw);
    ((__half2*)g_xh)[i*2]   = __halves2half2(hx, hy);
    ((__half2*)g_xh)[i*2+1] = __halves2half2(hz, hw);
    ((__half2*)g_xl)[i*2]   = __halves2half2(lx, ly);
    ((__half2*)g_xl)[i*2+1] = __halves2half2(lz, lw);
}

// ---------------------------------------------------------------------------
// Prep kernel B: transpose + split the 4 weight matrices.
// ---------------------------------------------------------------------------
__global__ __launch_bounds__(256) void split_w_kernel(
    const float* __restrict__ Wq, const float* __restrict__ Wk,
    const float* __restrict__ Wv, const float* __restrict__ Wo)
{
    __shared__ float t[32][33];
    const int z = blockIdx.z;
    const float* W = (z==0) ? Wq : (z==1) ? Wk : (z==2) ? Wv : Wo;
    __half* dh = (z < 3) ? (g_wth + (size_t)z * HID * HID) : g_woth;
    __half* dl = (z < 3) ? (g_wtl + (size_t)z * HID * HID) : g_wotl;
    const int n0 = blockIdx.x * 32, k0 = blockIdx.y * 32;
    const int tx = threadIdx.x, ty = threadIdx.y;

#pragma unroll
    for (int r = 0; r < 4; r++)
        t[ty + r*8][tx] = W[(size_t)(k0 + ty + r*8) * HID + n0 + tx];
    __syncthreads();
#pragma unroll
    for (int r = 0; r < 4; r++) {
        float v = t[tx][ty + r*8];     // = W[k0+tx][n0+ty+r*8]
        __half hv, lv;
        f16_split(v, hv, lv);
        size_t o = (size_t)(n0 + ty + r*8) * HID + k0 + tx;
        dh[o] = hv;
        dl[o] = lv;
    }
}

// ===========================================================================
// split-fp16 GEMM core (validated round 8)
// ===========================================================================
#define KP 40
#define PLANE (128*KP)
#define PB (PLANE*2)
#define GSMEM_BYTES (8*PB)

__device__ __forceinline__ void gemm_f16split(
    const __half* __restrict__ Agh, const __half* __restrict__ Agl,
    const __half* __restrict__ Bgh, const __half* __restrict__ Bgl,
    int tm0, int c0, __half* sm, float (*S)[8][4])
{
    const int tid  = threadIdx.x;
    const int warp = tid >> 5;
    const int lane = tid & 31;
    const int g  = lane >> 2;
    const int tg = lane & 3;
    const int wm0 = (warp >> 1) * 32;
    const int wn0 = (warp & 1) * 64;
    const uint32_t sb = (uint32_t)__cvta_generic_to_shared(sm);

#pragma unroll
    for (int mt = 0; mt < 2; mt++)
#pragma unroll
        for (int nt = 0; nt < 8; nt++)
#pragma unroll
            for (int j = 0; j < 4; j++) S[mt][nt][j] = 0.0f;

#define LOAD_STAGE(st, k0)                                                     \
    for (int i = tid; i < 512; i += 256) {                                     \
        int row = i >> 2, ch = i & 3;                                          \
        uint32_t so = (uint32_t)((st)*PB + row*(KP*2) + ch*16);                \
        size_t ga = (size_t)(tm0 + row) * HID + (k0) + ch*8;                   \
        size_t gb = (size_t)(c0  + row) * HID + (k0) + ch*8;                   \
        cp_async16_u(sb + so,        Agh + ga);                                \
        cp_async16_u(sb + 2*PB + so, Agl + ga);                                \
        cp_async16_u(sb + 4*PB + so, Bgh + gb);                                \
        cp_async16_u(sb + 6*PB + so, Bgl + gb);                                \
    }

    LOAD_STAGE(0, 0)
    CP_COMMIT();

    for (int kc = 0; kc < 16; kc++) {
        __syncthreads();
        if (kc + 1 < 16) {
            int ns = (kc + 1) & 1;
            int nk = (kc + 1) * 32;
            LOAD_STAGE(ns, nk)
            CP_COMMIT();
            CP_WAIT1();
        } else {
            CP_WAIT0();
        }
        __syncthreads();

        const int st = kc & 1;
        const __half* Ah = sm + st*PLANE;
        const __half* Al = sm + 2*PLANE + st*PLANE;
        const __half* Bh = sm + 4*PLANE + st*PLANE;
        const __half* Bl = sm + 6*PLANE + st*PLANE;

#pragma unroll
        for (int ks = 0; ks < 2; ks++) {
            const int ko = ks * 16;
            uint32_t ahi[2][4], alo[2][4];
#pragma unroll
            for (int mt = 0; mt < 2; mt++) {
                const __half* ah = Ah + (wm0 + mt*16)*KP + ko;
                const __half* al = Al + (wm0 + mt*16)*KP + ko;
                ahi[mt][0] = *(const uint32_t*)(ah + g*KP + 2*tg);
                ahi[mt][1] = *(const uint32_t*)(ah + (g+8)*KP + 2*tg);
                ahi[mt][2] = *(const uint32_t*)(ah + g*KP + 2*tg + 8);
                ahi[mt][3] = *(const uint32_t*)(ah + (g+8)*KP + 2*tg + 8);
                alo[mt][0] = *(const uint32_t*)(al + g*KP + 2*tg);
                alo[mt][1] = *(const uint32_t*)(al + (g+8)*KP + 2*tg);
                alo[mt][2] = *(const uint32_t*)(al + g*KP + 2*tg + 8);
                alo[mt][3] = *(const uint32_t*)(al + (g+8)*KP + 2*tg + 8);
            }
#pragma unroll
            for (int nt = 0; nt < 8; nt++) {
                const __half* bh = Bh + (wn0 + nt*8 + g)*KP + ko;
                const __half* bl = Bl + (wn0 + nt*8 + g)*KP + ko;
                uint32_t bhi[2], blo[2];
                bhi[0] = *(const uint32_t*)(bh + 2*tg);
                bhi[1] = *(const uint32_t*)(bh + 2*tg + 8);
                blo[0] = *(const uint32_t*)(bl + 2*tg);
                blo[1] = *(const uint32_t*)(bl + 2*tg + 8);
#pragma unroll
                for (int mt = 0; mt < 2; mt++) {
                    mma_f16(&S[mt][nt][0], ahi[mt], bhi);
                    mma_f16(&S[mt][nt][0], ahi[mt], blo);
                    mma_f16(&S[mt][nt][0], alo[mt], bhi);
                }
            }
        }
    }
#undef LOAD_STAGE
}

// ---------------------------------------------------------------------------
// Kernel 1: fused QKV projection (split-fp16). Outputs fp16 [b,h,n,d].
// ---------------------------------------------------------------------------
__global__ __launch_bounds__(256, 2) void qkv_f16_kernel(
    const float* __restrict__ bq, const float* __restrict__ bk,
    const float* __restrict__ bv)
{
    extern __shared__ __half gsm[];
    const int wsel = blockIdx.x >> 2;
    const int c0   = (blockIdx.x & 3) * 128;
    const __half* Bh = g_wth + (size_t)wsel * HID * HID;
    const __half* Bl = g_wtl + (size_t)wsel * HID * HID;
    const float* bias = (wsel==0) ? bq : ((wsel==1) ? bk : bv);
    __half* outb      = (wsel==0) ? g_q : ((wsel==1) ? g_k : g_v);
    const float scale = (wsel==0) ? QSCALE : 1.0f;
    const int tm0 = blockIdx.y * 128;

    float S[2][8][4];
    gemm_f16split(g_xh, g_xl, Bh, Bl, tm0, c0, gsm, S);

    const int tid  = threadIdx.x;
    const int warp = tid >> 5;
    const int lane = tid & 31;
    const int g  = lane >> 2;
    const int tg = lane & 3;
    const int wm0 = (warp >> 1) * 32;
    const int wn0 = (warp & 1) * 64;

    const int cbase = c0 + wn0;
    const int hh = cbase >> 6;

#pragma unroll
    for (int mt = 0; mt < 2; mt++) {
#pragma unroll
        for (int r = 0; r < 2; r++) {
            int t = tm0 + wm0 + mt*16 + r*8 + g;
            int b = t >> 12;
            int n = t & (NN - 1);
            __half* op = outb + (((size_t)(b * NH + hh)) * NN + n) * HD;
#pragma unroll
            for (int nt = 0; nt < 8; nt++) {
                int d0 = nt*8 + tg*2;
                float v0 = (S[mt][nt][2*r]   + bias[cbase + d0])     * scale;
                float v1 = (S[mt][nt][2*r+1] + bias[cbase + d0 + 1]) * scale;
                *(__half2*)(op + d0) = __floats2half2_rn(v0, v1);
            }
        }
    }
}

// ---------------------------------------------------------------------------
// Kernel 3: output projection (split-fp16). fp32 out.
// ---------------------------------------------------------------------------
__global__ __launch_bounds__(256, 2) void proj_f16_kernel(
    const float* __restrict__ bo, float* __restrict__ out)
{
    extern __shared__ __half gsm[];
    const int c0  = blockIdx.x * 128;
    const int tm0 = blockIdx.y * 128;

    float S[2][8][4];
    gemm_f16split(g_ah, g_al, g_woth, g_wotl, tm0, c0, gsm, S);

    const int tid  = threadIdx.x;
    const int warp = tid >> 5;
    const int lane = tid & 31;
    const int g  = lane >> 2;
    const int tg = lane & 3;
    const int wm0 = (warp >> 1) * 32;
    const int wn0 = (warp & 1) * 64;

#pragma unroll
    for (int mt = 0; mt < 2; mt++) {
#pragma unroll
        for (int r = 0; r < 2; r++) {
            int t = tm0 + wm0 + mt*16 + r*8 + g;
            float* op = out + (size_t)t * HID + c0 + wn0;
#pragma unroll
            for (int nt = 0; nt < 8; nt++) {
                int d0 = nt*8 + tg*2;
                float2 vv = make_float2(S[mt][nt][2*r]   + bo[c0 + wn0 + d0],
                                        S[mt][nt][2*r+1] + bo[c0 + wn0 + d0 + 1]);
                *(float2*)(op + d0) = vv;
            }
        }
    }
}

// ===========================================================================
// Kernel 2: flash attention, fp16 mma.sync, 8 warps x 16 query rows.
// Register-resident P (softmax accumulator regs ARE the PV A-fragments —
// no P smem round-trip). Q fragments hoisted (loop-invariant).
// All-ones mask fast path; K/V via ldmatrix.x4.
// ===========================================================================
#define QP 72
#define AOFF_Q  0
#define AOFF_K  (128*QP*2)                 // bytes
#define AOFF_V  (AOFF_K + 2*64*QP*2)
#define AOFF_MK (AOFF_V + 2*64*QP*2)
#define ATTN_SMEM (AOFF_MK + 2*64*4)
#define KVBUF (64*QP*2)

__global__ __launch_bounds__(256, 2) void attn_fp16_kernel(const float* __restrict__ mask)
{
    extern __shared__ char smc[];
    const uint32_t sbase = (uint32_t)__cvta_generic_to_shared(smc);

    const int tid  = threadIdx.x;
    const int warp = tid >> 5;
    const int lane = tid & 31;
    const int g  = lane >> 2;
    const int tg = lane & 3;
    const int wq0 = warp * 16;             // 16 query rows per warp

    // ldmatrix lane->address components
    const int lrow8  = (lane & 7) + ((lane >> 3) & 1) * 8;   // x4 A row
    const int lcol16 = (lane >> 4) * 16;                     // x4 A col byte offset
    const int kbrow  = (lane & 7) + ((lane >> 4) & 1) * 8;   // K B x4 row
    const int kbcol  = ((lane >> 3) & 1) * 16;               // K B x4 col
    const int vbrow  = lane & 15;                            // V B x4t key row
    const int vbcol  = (lane >> 4) * 16;                     // V B x4t col

    const int bh  = blockIdx.x;
    const int b   = bh >> 3;
    const int hd  = bh & 7;
    const int qt0 = blockIdx.y * 128;

    const __half* qb = g_q + (size_t)bh * NN * HD;
    const __half* kb = g_k + (size_t)bh * NN * HD;
    const __half* vb = g_v + (size_t)bh * NN * HD;
    const float*  mb = mask + (size_t)b * NN;

    // ---- all-ones mask detection (uniform per block) ----
    int ok = 1;
    for (int i = tid; i < NN / 4; i += 256) {
        float4 mv = ((const float4*)mb)[i];
        ok &= (mv.x == 1.0f) & (mv.y == 1.0f) & (mv.z == 1.0f) & (mv.w == 1.0f);
    }
    const int allone = __syncthreads_and(ok);

    // prologue: Q + tile 0 (K/V/mask) in one cp.async group
    for (int i = tid; i < 1024; i += 256) {
        int row = i >> 3, ch = i & 7;
        cp_async16_u(sbase + AOFF_Q + row*(QP*2) + ch*16,
                     qb + (size_t)(qt0 + row) * HD + ch*8);
    }
    for (int i = tid; i < 512; i += 256) {
        int row = i >> 3, ch = i & 7;
        cp_async16_u(sbase + AOFF_K + row*(QP*2) + ch*16, kb + (size_t)row * HD + ch*8);
        cp_async16_u(sbase + AOFF_V + row*(QP*2) + ch*16, vb + (size_t)row * HD + ch*8);
    }
    if (!allone && tid < 16) cp_async16_u(sbase + AOFF_MK + tid*16, mb + tid*4);
    CP_COMMIT();

    float mq[2];
    mq[0] = mb[qt0 + wq0 + g];
    mq[1] = mb[qt0 + wq0 + 8 + g];

    uint32_t qa[4][4];                     // hoisted Q fragments (loaded at it==0)
    float O[8][4];
#pragma unroll
    for (int dt = 0; dt < 8; dt++)
#pragma unroll
        for (int j = 0; j < 4; j++) O[dt][j] = 0.0f;
    float lsum[2] = {0.f, 0.f};

    for (int it = 0; it < 64; it++) {
        const int buf = it & 1;
        __syncthreads();
        if (it + 1 < 64) {
            const int nb = (it + 1) & 1;
            const __half* kg = kb + (size_t)(it + 1) * 64 * HD;
            const __half* vg = vb + (size_t)(it + 1) * 64 * HD;
            for (int i = tid; i < 512; i += 256) {
                int row = i >> 3, ch = i & 7;
                cp_async16_u(sbase + AOFF_K + nb*KVBUF + row*(QP*2) + ch*16,
                             kg + (size_t)row * HD + ch*8);
                cp_async16_u(sbase + AOFF_V + nb*KVBUF + row*(QP*2) + ch*16,
                             vg + (size_t)row * HD + ch*8);
            }
            if (!allone && tid < 16) cp_async16_u(sbase + AOFF_MK + nb*256 + tid*16,
                                                  mb + (it + 1)*64 + tid*4);
            CP_COMMIT();
            CP_WAIT1();
        } else {
            CP_WAIT0();
        }
        __syncthreads();

        if (it == 0) {
            // load loop-invariant Q fragments once
#pragma unroll
            for (int kc = 0; kc < 4; kc++)
                ldmx4(qa[kc], sbase + AOFF_Q +
                      (uint32_t)((wq0 + lrow8)*(QP*2) + lcol16 + kc*32));
        }

        const uint32_t kbase = sbase + AOFF_K + buf*KVBUF;
        const uint32_t vbase = sbase + AOFF_V + buf*KVBUF;
        const float*   mks  = (const float*)(smc + AOFF_MK + buf*256);

        // ---- S = Q @ K^T  (warp: 16 rows x 64 cols; 4 k-chunks of 16) ----
        float S[8][4];
#pragma unroll
        for (int nt = 0; nt < 8; nt++)
#pragma unroll
            for (int j = 0; j < 4; j++) S[nt][j] = 0.0f;

#pragma unroll
        for (int kc = 0; kc < 4; kc++) {
#pragma unroll
            for (int ntp = 0; ntp < 4; ntp++) {
                uint32_t bf[4];
                ldmx4(bf, kbase + (uint32_t)((ntp*16 + kbrow)*(QP*2) + kbcol + kc*32));
                mma_f16(&S[2*ntp][0],   qa[kc], bf);
                mma_f16(&S[2*ntp+1][0], qa[kc], bf + 2);
            }
        }

        // ---- softmax; P stays in registers as PV A-fragments ----
        // pa[nt][0] = h2(P[row g][nt*8+2tg], +1), pa[nt][1] = rows g+8.
        uint32_t pa[8][2];
        if (allone) {
#pragma unroll
            for (int nt = 0; nt < 8; nt++) {
                float p0 = __expf(S[nt][0]);
                float p1 = __expf(S[nt][1]);
                float p2 = __expf(S[nt][2]);
                float p3 = __expf(S[nt][3]);
                lsum[0] += p0 + p1;
                lsum[1] += p2 + p3;
                pa[nt][0] = h2u_pack(p0, p1);
                pa[nt][1] = h2u_pack(p2, p3);
            }
        } else {
#pragma unroll
            for (int nt = 0; nt < 8; nt++) {
                int c0 = nt*8 + 2*tg;
                float mk0 = mks[c0], mk1 = mks[c0 + 1];
                float p0 = __expf(S[nt][0] + (1.0f - mq[0]*mk0) * (-1.0e6f));
                float p1 = __expf(S[nt][1] + (1.0f - mq[0]*mk1) * (-1.0e6f));
                float p2 = __expf(S[nt][2] + (1.0f - mq[1]*mk0) * (-1.0e6f));
                float p3 = __expf(S[nt][3] + (1.0f - mq[1]*mk1) * (-1.0e6f));
                lsum[0] += p0 + p1;
                lsum[1] += p2 + p3;
                pa[nt][0] = h2u_pack(p0, p1);
                pa[nt][1] = h2u_pack(p2, p3);
            }
        }

        // ---- O += P @ V  (4 k-chunks of 16 keys; A-fragment from registers) ----
#pragma unroll
        for (int kc = 0; kc < 4; kc++) {
            uint32_t a[4] = { pa[2*kc][0], pa[2*kc][1], pa[2*kc+1][0], pa[2*kc+1][1] };
#pragma unroll
            for (int dtp = 0; dtp < 4; dtp++) {
                uint32_t bf[4];
                ldmx4t(bf, vbase + (uint32_t)((kc*16 + vbrow)*(QP*2) + dtp*32 + vbcol));
                mma_f16(&O[2*dtp][0],   a, bf);
                mma_f16(&O[2*dtp+1][0], a, bf + 2);
            }
        }
    }

    // ---- epilogue: normalize, split to fp16 hi/lo planes ----
#pragma unroll
    for (int r = 0; r < 2; r++) {
        float s = lsum[r];
        s += __shfl_xor_sync(0xffffffffu, s, 1);
        s += __shfl_xor_sync(0xffffffffu, s, 2);
        float inv = 1.0f / s;
        int row = qt0 + wq0 + r*8 + g;
        size_t base = ((size_t)(b * NN + row)) * HID + hd * HD;
#pragma unroll
        for (int dt = 0; dt < 8; dt++) {
            float v0 = O[dt][2*r] * inv;
            float v1 = O[dt][2*r+1] * inv;
            __half h0, l0, h1, l1;
            f16_split(v0, h0, l0);
            f16_split(v1, h1, l1);
            size_t o = base + dt*8 + 2*tg;
            *(__half2*)(g_ah + o) = __halves2half2(h0, h1);
            *(__half2*)(g_al + o) = __halves2half2(l0, l1);
        }
    }
}

// ---------------------------------------------------------------------------
extern "C" void kernel_launch(void* const* d_in, const int* in_sizes, int n_in,
                              void* d_out, int out_size)
{
    const float* x    = (const float*)d_in[0];
    const float* mask = (const float*)d_in[1];
    const float* Wq   = (const float*)d_in[2];
    const float* bq   = (const float*)d_in[3];
    const float* Wk   = (const float*)d_in[4];
    const float* bk   = (const float*)d_in[5];
    const float* Wv   = (const float*)d_in[6];
    const float* bv   = (const float*)d_in[7];
    const float* Wo   = (const float*)d_in[8];
    const float* bo   = (const float*)d_in[9];
    float* out = (float*)d_out;

    cudaFuncSetAttribute(attn_fp16_kernel,
                         cudaFuncAttributeMaxDynamicSharedMemorySize, ATTN_SMEM);
    cudaFuncSetAttribute(qkv_f16_kernel,
                         cudaFuncAttributeMaxDynamicSharedMemorySize, GSMEM_BYTES);
    cudaFuncSetAttribute(proj_f16_kernel,
                         cudaFuncAttributeMaxDynamicSharedMemorySize, GSMEM_BYTES);

    split_x_kernel<<<4096, 256>>>(x);
    split_w_kernel<<<dim3(16, 16, 4), dim3(32, 8)>>>(Wq, Wk, Wv, Wo);

    dim3 qkv_grid(12, MTOK / 128);
    qkv_f16_kernel<<<qkv_grid, 256, GSMEM_BYTES>>>(bq, bk, bv);

    dim3 attn_grid(BB * NH, NN / 128);
    attn_fp16_kernel<<<attn_grid, 256, ATTN_SMEM>>>(mask);

    dim3 proj_grid(HID / 128, MTOK / 128);
    proj_f16_kernel<<<proj_grid, 256, GSMEM_BYTES>>>(bo, out);
}